// round 5
// baseline (speedup 1.0000x reference)
#include <cuda_runtime.h>

// BettingLoss: B=4194304 rows, T=6 traps, 3 x f32 [B,T] inputs.
// Streaming HBM-bound reduction -> [loss, batch_profit, num_bets] (f32 x3).

#define TPB  256
#define NBLK 2048

static constexpr int   B_ROWS  = 4194304;
static constexpr int   T_TRAPS = 6;
static constexpr float ALPHA_F = 1.1f;
static constexpr float BET_PCT = 0.02f;
static constexpr float COMM_C  = 0.95f;            // 1 - commission
static constexpr float PAYOUT  = 0.02f * 0.95f;    // bet_pct * (1-commission)

__device__ float4 g_part[NBLK];   // x=sum_bet_ep, y=sum_profit, z=num_bets, w=sum_maxp

__device__ __forceinline__ void process_row(const float* __restrict__ pp,
                                            const float* __restrict__ tw,
                                            const float* __restrict__ mo,
                                            float& s_ep, float& s_pr,
                                            float& s_nb, float& s_mx)
{
    bool has_valid = false;
    float maxp = -1e30f;
#pragma unroll
    for (int t = 0; t < T_TRAPS; t++) {
        has_valid = has_valid || (mo[t] > 0.0f);
        maxp = fmaxf(maxp, pp[t]);
    }
    s_mx += maxp;

    // expected profit per trap; zeroed if the race has no valid odds
    float best_ep = -1e30f;
    int   best_i  = 0;
#pragma unroll
    for (int t = 0; t < T_TRAPS; t++) {
        float ep = (mo[t] * ALPHA_F * pp[t] - 1.0f) * PAYOUT;
        if (!has_valid) ep = 0.0f;
        if (ep > best_ep) { best_ep = ep; best_i = t; }   // first-max (jnp.argmax)
    }

    bool bet = (best_ep > 0.0f) && has_valid;
    if (bet) {
        s_ep += best_ep;
        s_nb += 1.0f;
        float odds_b = mo[best_i];
        float win_b  = tw[best_i];
        float prof = (win_b > 0.5f)
                   ? (odds_b * ALPHA_F * BET_PCT - BET_PCT) * COMM_C
                   : -PAYOUT;
        s_pr += prof;
    }
}

__global__ void __launch_bounds__(TPB)
betting_main(const float* __restrict__ pp,
             const float* __restrict__ tw,
             const float* __restrict__ mo)
{
    float s_ep = 0.0f, s_pr = 0.0f, s_nb = 0.0f, s_mx = 0.0f;

    const int npairs = B_ROWS / 2;                 // 2 rows per iteration -> 48B aligned
    const int stride = gridDim.x * blockDim.x;

    for (int pr = blockIdx.x * blockDim.x + threadIdx.x; pr < npairs; pr += stride) {
        size_t base = (size_t)pr * 12;             // 12 floats = 2 rows
        const float4* p4 = (const float4*)(pp + base);
        const float4* w4 = (const float4*)(tw + base);
        const float4* o4 = (const float4*)(mo + base);

        float4 pa = p4[0], pb = p4[1], pc = p4[2];
        float4 wa = w4[0], wb = w4[1], wc = w4[2];
        float4 oa = o4[0], ob = o4[1], oc = o4[2];

        float P[12] = {pa.x, pa.y, pa.z, pa.w, pb.x, pb.y, pb.z, pb.w, pc.x, pc.y, pc.z, pc.w};
        float W[12] = {wa.x, wa.y, wa.z, wa.w, wb.x, wb.y, wb.z, wb.w, wc.x, wc.y, wc.z, wc.w};
        float O[12] = {oa.x, oa.y, oa.z, oa.w, ob.x, ob.y, ob.z, ob.w, oc.x, oc.y, oc.z, oc.w};

        process_row(P,     W,     O,     s_ep, s_pr, s_nb, s_mx);
        process_row(P + 6, W + 6, O + 6, s_ep, s_pr, s_nb, s_mx);
    }

    // warp reduce
#pragma unroll
    for (int off = 16; off > 0; off >>= 1) {
        s_ep += __shfl_down_sync(0xffffffffu, s_ep, off);
        s_pr += __shfl_down_sync(0xffffffffu, s_pr, off);
        s_nb += __shfl_down_sync(0xffffffffu, s_nb, off);
        s_mx += __shfl_down_sync(0xffffffffu, s_mx, off);
    }

    __shared__ float4 sm[TPB / 32];
    int lane = threadIdx.x & 31;
    int warp = threadIdx.x >> 5;
    if (lane == 0) sm[warp] = make_float4(s_ep, s_pr, s_nb, s_mx);
    __syncthreads();

    if (warp == 0) {
        float4 v = (lane < TPB / 32) ? sm[lane] : make_float4(0.f, 0.f, 0.f, 0.f);
#pragma unroll
        for (int off = (TPB / 32) / 2; off > 0; off >>= 1) {
            v.x += __shfl_down_sync(0xffffffffu, v.x, off);
            v.y += __shfl_down_sync(0xffffffffu, v.y, off);
            v.z += __shfl_down_sync(0xffffffffu, v.z, off);
            v.w += __shfl_down_sync(0xffffffffu, v.w, off);
        }
        if (lane == 0) g_part[blockIdx.x] = v;
    }
}

__global__ void __launch_bounds__(1024)
betting_final(float* __restrict__ out, int out_size)
{
    __shared__ float4 sm[1024];
    int t = threadIdx.x;
    float4 a = g_part[t];
    float4 b = g_part[t + 1024];
    sm[t] = make_float4(a.x + b.x, a.y + b.y, a.z + b.z, a.w + b.w);
    __syncthreads();

#pragma unroll
    for (int s = 512; s > 0; s >>= 1) {
        if (t < s) {
            float4 u = sm[t], v = sm[t + s];
            sm[t] = make_float4(u.x + v.x, u.y + v.y, u.z + v.z, u.w + v.w);
        }
        __syncthreads();
    }

    if (t == 0) {
        float sum_ep = sm[0].x;
        float sum_pr = sm[0].y;
        float nbets  = sm[0].z;
        float sum_mx = sm[0].w;

        float fallback = -(sum_mx / (float)B_ROWS) * 0.1f;
        float tep  = (nbets > 0.0f) ? sum_ep : fallback;
        float loss = -tep / (float)B_ROWS;

        if (out_size > 0) out[0] = loss;
        if (out_size > 1) out[1] = sum_pr;
        if (out_size > 2) out[2] = nbets;
    }
}

extern "C" void kernel_launch(void* const* d_in, const int* in_sizes, int n_in,
                              void* d_out, int out_size)
{
    const float* pp = (const float*)d_in[0];   // predicted_probs [B,T]
    const float* tw = (const float*)d_in[1];   // true_winners    [B,T]
    const float* mo = (const float*)d_in[2];   // market_odds     [B,T]
    float* out = (float*)d_out;

    betting_main<<<NBLK, TPB>>>(pp, tw, mo);
    betting_final<<<1, 1024>>>(out, out_size);
}

// round 6
// speedup vs baseline: 1.5594x; 1.5594x over previous
#include <cuda_runtime.h>

// BettingLoss: B=4194304 rows, T=6 traps, 3 x f32 [B,T] inputs.
// Single fused streaming-reduction kernel -> [loss, batch_profit, num_bets].

#define TPB   256
#define NBLK  2048
#define NITER 4            // (B/2 pairs) / (NBLK*TPB threads) = 4 exactly

static constexpr int   B_ROWS  = 4194304;
static constexpr float PAYOUT  = (float)(0.02 * 0.95);          // bet_pct*(1-comm) = 0.019
static constexpr float K_EP    = (float)(1.1 * 0.02 * 0.95);    // alpha*payout     = 0.0209

__device__ float4       g_part[NBLK];  // x=sum_bet_ep, y=sum_profit, z=num_bets, w=sum_maxp
__device__ unsigned int g_count = 0;

__device__ __forceinline__ void process_row(const float* __restrict__ P,
                                            const float* __restrict__ W,
                                            const float* __restrict__ O,
                                            float& s_ep, float& s_pr,
                                            float& s_nb, float& s_mx)
{
    // max predicted prob (fallback term)
    s_mx += fmaxf(fmaxf(fmaxf(P[0], P[1]), fmaxf(P[2], P[3])), fmaxf(P[4], P[5]));

    // argmax of ep == argmax of q = mo*pp (ep affine increasing in q).
    // has_valid is redundant: all-zero odds -> q_max=0 -> best_ep<0 -> no bet.
    float bq = O[0] * P[0];
    float bo = O[0];
    float bw = W[0];
#pragma unroll
    for (int t = 1; t < 6; t++) {
        float q = O[t] * P[t];
        bool  g = q > bq;               // strict: first-max (jnp.argmax semantics)
        bq = g ? q    : bq;
        bo = g ? O[t] : bo;
        bw = g ? W[t] : bw;
    }

    float best_ep = fmaf(bq, K_EP, -PAYOUT);
    if (best_ep > 0.0f) {
        s_ep += best_ep;
        s_nb += 1.0f;
        s_pr += (bw > 0.5f) ? fmaf(bo, K_EP, -PAYOUT) : -PAYOUT;
    }
}

__device__ __forceinline__ float4 warp_reduce4(float4 v)
{
#pragma unroll
    for (int off = 16; off > 0; off >>= 1) {
        v.x += __shfl_down_sync(0xffffffffu, v.x, off);
        v.y += __shfl_down_sync(0xffffffffu, v.y, off);
        v.z += __shfl_down_sync(0xffffffffu, v.z, off);
        v.w += __shfl_down_sync(0xffffffffu, v.w, off);
    }
    return v;
}

__global__ void __launch_bounds__(TPB)
betting_fused(const float* __restrict__ pp,
              const float* __restrict__ tw,
              const float* __restrict__ mo,
              float* __restrict__ out, int out_size)
{
    float s_ep = 0.0f, s_pr = 0.0f, s_nb = 0.0f, s_mx = 0.0f;

    const unsigned tid = blockIdx.x * TPB + threadIdx.x;
    const unsigned TOT = NBLK * TPB;

#pragma unroll
    for (int it = 0; it < NITER; it++) {
        size_t base = (size_t)(tid + (unsigned)it * TOT) * 12u;   // 12 floats = 2 rows

        const float4* p4 = (const float4*)(pp + base);
        const float4* w4 = (const float4*)(tw + base);
        const float4* o4 = (const float4*)(mo + base);

        float4 pa = p4[0], pb = p4[1], pc = p4[2];
        float4 wa = w4[0], wb = w4[1], wc = w4[2];
        float4 oa = o4[0], ob = o4[1], oc = o4[2];

        float P[12] = {pa.x,pa.y,pa.z,pa.w, pb.x,pb.y,pb.z,pb.w, pc.x,pc.y,pc.z,pc.w};
        float W[12] = {wa.x,wa.y,wa.z,wa.w, wb.x,wb.y,wb.z,wb.w, wc.x,wc.y,wc.z,wc.w};
        float O[12] = {oa.x,oa.y,oa.z,oa.w, ob.x,ob.y,ob.z,ob.w, oc.x,oc.y,oc.z,oc.w};

        process_row(P,     W,     O,     s_ep, s_pr, s_nb, s_mx);
        process_row(P + 6, W + 6, O + 6, s_ep, s_pr, s_nb, s_mx);
    }

    // ---- block reduce ----
    float4 v = warp_reduce4(make_float4(s_ep, s_pr, s_nb, s_mx));

    __shared__ float4 sm[TPB / 32];
    const int lane = threadIdx.x & 31;
    const int warp = threadIdx.x >> 5;
    if (lane == 0) sm[warp] = v;
    __syncthreads();

    __shared__ bool isLast;
    if (warp == 0) {
        float4 b = (lane < TPB / 32) ? sm[lane] : make_float4(0.f, 0.f, 0.f, 0.f);
#pragma unroll
        for (int off = (TPB / 32) / 2; off > 0; off >>= 1) {
            b.x += __shfl_down_sync(0xffffffffu, b.x, off);
            b.y += __shfl_down_sync(0xffffffffu, b.y, off);
            b.z += __shfl_down_sync(0xffffffffu, b.z, off);
            b.w += __shfl_down_sync(0xffffffffu, b.w, off);
        }
        if (lane == 0) {
            g_part[blockIdx.x] = b;
            __threadfence();
            unsigned prev = atomicAdd(&g_count, 1u);
            isLast = (prev == NBLK - 1u);
        }
    }
    __syncthreads();
    if (!isLast) return;

    // ---- last block: final reduce of NBLK partials ----
    float4 acc = make_float4(0.f, 0.f, 0.f, 0.f);
#pragma unroll
    for (int i = 0; i < NBLK / TPB; i++) {
        float4 p = g_part[threadIdx.x + i * TPB];
        acc.x += p.x; acc.y += p.y; acc.z += p.z; acc.w += p.w;
    }
    acc = warp_reduce4(acc);
    if (lane == 0) sm[warp] = acc;
    __syncthreads();

    if (warp == 0) {
        float4 b = (lane < TPB / 32) ? sm[lane] : make_float4(0.f, 0.f, 0.f, 0.f);
#pragma unroll
        for (int off = (TPB / 32) / 2; off > 0; off >>= 1) {
            b.x += __shfl_down_sync(0xffffffffu, b.x, off);
            b.y += __shfl_down_sync(0xffffffffu, b.y, off);
            b.z += __shfl_down_sync(0xffffffffu, b.z, off);
            b.w += __shfl_down_sync(0xffffffffu, b.w, off);
        }
        if (lane == 0) {
            const float invB = 1.0f / (float)B_ROWS;   // B = 2^22: exact
            float fallback = -(b.w * invB) * 0.1f;
            float tep  = (b.z > 0.0f) ? b.x : fallback;
            float loss = -tep * invB;

            if (out_size > 0) out[0] = loss;
            if (out_size > 1) out[1] = b.y;
            if (out_size > 2) out[2] = b.z;

            g_count = 0;                               // reset for next graph replay
        }
    }
}

extern "C" void kernel_launch(void* const* d_in, const int* in_sizes, int n_in,
                              void* d_out, int out_size)
{
    const float* pp = (const float*)d_in[0];   // predicted_probs [B,T]
    const float* tw = (const float*)d_in[1];   // true_winners    [B,T]
    const float* mo = (const float*)d_in[2];   // market_odds     [B,T]

    betting_fused<<<NBLK, TPB>>>(pp, tw, mo, (float*)d_out, out_size);
}

// round 7
// speedup vs baseline: 1.6020x; 1.0273x over previous
#include <cuda_runtime.h>

// BettingLoss: B=4194304 rows, T=6 traps, 3 x f32 [B,T] inputs.
// Single fused streaming-reduction kernel -> [loss, batch_profit, num_bets].
// One row per thread per iteration, float2 loads (row stride 24B is 8-aligned),
// low register pressure -> 6 blocks/SM for DRAM latency hiding.

#define TPB   256
#define NBLK  2048
#define NITER 8            // B / (NBLK*TPB) = 8 exactly

static constexpr int   B_ROWS  = 4194304;
static constexpr float PAYOUT  = (float)(0.02 * 0.95);          // bet_pct*(1-comm) = 0.019
static constexpr float K_EP    = (float)(1.1 * 0.02 * 0.95);    // alpha*payout     = 0.0209

__device__ float4       g_part[NBLK];  // x=sum_bet_ep, y=sum_profit, z=num_bets, w=sum_maxp
__device__ unsigned int g_count = 0;

__device__ __forceinline__ float4 warp_reduce4(float4 v)
{
#pragma unroll
    for (int off = 16; off > 0; off >>= 1) {
        v.x += __shfl_down_sync(0xffffffffu, v.x, off);
        v.y += __shfl_down_sync(0xffffffffu, v.y, off);
        v.z += __shfl_down_sync(0xffffffffu, v.z, off);
        v.w += __shfl_down_sync(0xffffffffu, v.w, off);
    }
    return v;
}

__global__ void __launch_bounds__(TPB, 6)
betting_fused(const float* __restrict__ pp,
              const float* __restrict__ tw,
              const float* __restrict__ mo,
              float* __restrict__ out, int out_size)
{
    float s_ep = 0.0f, s_pr = 0.0f, s_nb = 0.0f, s_mx = 0.0f;

    const unsigned tid = blockIdx.x * TPB + threadIdx.x;
    const unsigned TOT = NBLK * TPB;

#pragma unroll 2
    for (int it = 0; it < NITER; it++) {
        size_t base = (size_t)(tid + (unsigned)it * TOT) * 6u;    // 6 floats = 1 row, 8B aligned

        const float2* p2 = (const float2*)(pp + base);
        const float2* w2 = (const float2*)(tw + base);
        const float2* o2 = (const float2*)(mo + base);

        float2 pa = p2[0], pb = p2[1], pc = p2[2];
        float2 oa = o2[0], ob = o2[1], oc = o2[2];
        float2 wa = w2[0], wb = w2[1], wc = w2[2];

        // fallback term: max predicted prob
        s_mx += fmaxf(fmaxf(fmaxf(pa.x, pa.y), fmaxf(pb.x, pb.y)),
                      fmaxf(pc.x, pc.y));

        // argmax of ep == argmax of q = mo*pp (ep affine increasing in q).
        // has_valid is redundant: all-zero odds -> q_max = 0 -> best_ep < 0 -> no bet.
        float q0 = oa.x * pa.x, q1 = oa.y * pa.y;
        float q2 = ob.x * pb.x, q3 = ob.y * pb.y;
        float q4 = oc.x * pc.x, q5 = oc.y * pc.y;

        float bq = q0, bo = oa.x, bw = wa.x;
        bool g;
        g = q1 > bq; bq = g ? q1 : bq; bo = g ? oa.y : bo; bw = g ? wa.y : bw;
        g = q2 > bq; bq = g ? q2 : bq; bo = g ? ob.x : bo; bw = g ? wb.x : bw;
        g = q3 > bq; bq = g ? q3 : bq; bo = g ? ob.y : bo; bw = g ? wb.y : bw;
        g = q4 > bq; bq = g ? q4 : bq; bo = g ? oc.x : bo; bw = g ? wc.x : bw;
        g = q5 > bq; bq = g ? q5 : bq; bo = g ? oc.y : bo; bw = g ? wc.y : bw;

        float best_ep = fmaf(bq, K_EP, -PAYOUT);
        if (best_ep > 0.0f) {
            s_ep += best_ep;
            s_nb += 1.0f;
            s_pr += (bw > 0.5f) ? fmaf(bo, K_EP, -PAYOUT) : -PAYOUT;
        }
    }

    // ---- block reduce ----
    float4 v = warp_reduce4(make_float4(s_ep, s_pr, s_nb, s_mx));

    __shared__ float4 sm[TPB / 32];
    const int lane = threadIdx.x & 31;
    const int warp = threadIdx.x >> 5;
    if (lane == 0) sm[warp] = v;
    __syncthreads();

    __shared__ bool isLast;
    if (warp == 0) {
        float4 b = (lane < TPB / 32) ? sm[lane] : make_float4(0.f, 0.f, 0.f, 0.f);
#pragma unroll
        for (int off = (TPB / 32) / 2; off > 0; off >>= 1) {
            b.x += __shfl_down_sync(0xffffffffu, b.x, off);
            b.y += __shfl_down_sync(0xffffffffu, b.y, off);
            b.z += __shfl_down_sync(0xffffffffu, b.z, off);
            b.w += __shfl_down_sync(0xffffffffu, b.w, off);
        }
        if (lane == 0) {
            g_part[blockIdx.x] = b;
            __threadfence();
            unsigned prev = atomicAdd(&g_count, 1u);
            isLast = (prev == NBLK - 1u);
        }
    }
    __syncthreads();
    if (!isLast) return;

    // ---- last block: final reduce of NBLK partials ----
    float4 acc = make_float4(0.f, 0.f, 0.f, 0.f);
#pragma unroll
    for (int i = 0; i < NBLK / TPB; i++) {
        float4 p = g_part[threadIdx.x + i * TPB];
        acc.x += p.x; acc.y += p.y; acc.z += p.z; acc.w += p.w;
    }
    acc = warp_reduce4(acc);
    if (lane == 0) sm[warp] = acc;
    __syncthreads();

    if (warp == 0) {
        float4 b = (lane < TPB / 32) ? sm[lane] : make_float4(0.f, 0.f, 0.f, 0.f);
#pragma unroll
        for (int off = (TPB / 32) / 2; off > 0; off >>= 1) {
            b.x += __shfl_down_sync(0xffffffffu, b.x, off);
            b.y += __shfl_down_sync(0xffffffffu, b.y, off);
            b.z += __shfl_down_sync(0xffffffffu, b.z, off);
            b.w += __shfl_down_sync(0xffffffffu, b.w, off);
        }
        if (lane == 0) {
            const float invB = 1.0f / (float)B_ROWS;   // B = 2^22: exact
            float fallback = -(b.w * invB) * 0.1f;
            float tep  = (b.z > 0.0f) ? b.x : fallback;
            float loss = -tep * invB;

            if (out_size > 0) out[0] = loss;
            if (out_size > 1) out[1] = b.y;
            if (out_size > 2) out[2] = b.z;

            g_count = 0;                               // reset for next graph replay
        }
    }
}

extern "C" void kernel_launch(void* const* d_in, const int* in_sizes, int n_in,
                              void* d_out, int out_size)
{
    const float* pp = (const float*)d_in[0];   // predicted_probs [B,T]
    const float* tw = (const float*)d_in[1];   // true_winners    [B,T]
    const float* mo = (const float*)d_in[2];   // market_odds     [B,T]

    betting_fused<<<NBLK, TPB>>>(pp, tw, mo, (float*)d_out, out_size);
}